// round 3
// baseline (speedup 1.0000x reference)
#include <cuda_runtime.h>
#include <cuda_bf16.h>

#define B_ 2
#define N_ 2048
#define DIM_ 1024
#define H_ 16
#define DH_ 64
#define INNER_ 1024
#define SCALE_ 0.125f

// Scratch (device globals: no cudaMalloc allowed)
__device__ float g_qkv[B_ * N_ * 3 * INNER_];   // [B,N,3*INNER]   50.3 MB
__device__ float g_q[B_ * H_ * N_ * DH_];       // [B,H,N,DH]      16.8 MB
__device__ float g_k[B_ * H_ * N_ * DH_];
__device__ float g_v[B_ * H_ * N_ * DH_];
__device__ float g_att[B_ * N_ * INNER_];       // [B,N,INNER]     16.8 MB

// ---------------------------------------------------------------------------
// SGEMM (NT): C[m,n] = sum_k A[m,k] * B[n,k]  (+ bias[n] if bias != null)
// A: [M,K] row-major, B: [Ncol,K] row-major. 128x128 tile, BK=16, 256 thr,
// 8x8 micro-tile per thread.
// ---------------------------------------------------------------------------
__global__ __launch_bounds__(256) void sgemm_nt(
    const float* __restrict__ A, const float* __restrict__ Bm,
    float* __restrict__ C, const float* __restrict__ bias,
    int M, int Ncol, int K)
{
    __shared__ __align__(16) float As[16][132];
    __shared__ __align__(16) float Bs[16][132];

    const int tid = threadIdx.x;
    const int bm = blockIdx.y * 128;
    const int bn = blockIdx.x * 128;
    const int tx = tid & 15;       // col group (8 cols)
    const int ty = tid >> 4;       // row group (8 rows)
    const int lr = tid >> 2;       // load row 0..63 (and +64)
    const int lk = (tid & 3) << 2; // load k offset 0,4,8,12

    const float* Ap = A + (size_t)(bm + lr) * K + lk;
    const float* Bp = Bm + (size_t)(bn + lr) * K + lk;

    float acc[8][8];
#pragma unroll
    for (int i = 0; i < 8; i++)
#pragma unroll
        for (int j = 0; j < 8; j++) acc[i][j] = 0.f;

    for (int kt = 0; kt < K; kt += 16) {
        float4 a0 = *(const float4*)(Ap + kt);
        float4 a1 = *(const float4*)(Ap + (size_t)64 * K + kt);
        float4 b0 = *(const float4*)(Bp + kt);
        float4 b1 = *(const float4*)(Bp + (size_t)64 * K + kt);
        __syncthreads();
        As[lk + 0][lr] = a0.x; As[lk + 1][lr] = a0.y; As[lk + 2][lr] = a0.z; As[lk + 3][lr] = a0.w;
        As[lk + 0][lr + 64] = a1.x; As[lk + 1][lr + 64] = a1.y; As[lk + 2][lr + 64] = a1.z; As[lk + 3][lr + 64] = a1.w;
        Bs[lk + 0][lr] = b0.x; Bs[lk + 1][lr] = b0.y; Bs[lk + 2][lr] = b0.z; Bs[lk + 3][lr] = b0.w;
        Bs[lk + 0][lr + 64] = b1.x; Bs[lk + 1][lr + 64] = b1.y; Bs[lk + 2][lr + 64] = b1.z; Bs[lk + 3][lr + 64] = b1.w;
        __syncthreads();
#pragma unroll
        for (int kk = 0; kk < 16; kk++) {
            float ar[8], br[8];
            *(float4*)(ar)     = *(const float4*)(&As[kk][ty * 8]);
            *(float4*)(ar + 4) = *(const float4*)(&As[kk][ty * 8 + 4]);
            *(float4*)(br)     = *(const float4*)(&Bs[kk][tx * 8]);
            *(float4*)(br + 4) = *(const float4*)(&Bs[kk][tx * 8 + 4]);
#pragma unroll
            for (int i = 0; i < 8; i++)
#pragma unroll
                for (int j = 0; j < 8; j++)
                    acc[i][j] = fmaf(ar[i], br[j], acc[i][j]);
        }
    }

    float bb[8];
#pragma unroll
    for (int j = 0; j < 8; j++) bb[j] = bias ? bias[bn + tx * 8 + j] : 0.f;

#pragma unroll
    for (int i = 0; i < 8; i++) {
        float* Crow = C + (size_t)(bm + ty * 8 + i) * Ncol + bn + tx * 8;
        float4 v0, v1;
        v0.x = acc[i][0] + bb[0]; v0.y = acc[i][1] + bb[1];
        v0.z = acc[i][2] + bb[2]; v0.w = acc[i][3] + bb[3];
        v1.x = acc[i][4] + bb[4]; v1.y = acc[i][5] + bb[5];
        v1.z = acc[i][6] + bb[6]; v1.w = acc[i][7] + bb[7];
        *(float4*)(Crow) = v0;
        *(float4*)(Crow + 4) = v1;
    }
}

// ---------------------------------------------------------------------------
// RoPE + reshape [B,N,3*INNER] -> q,k (rotary applied), v in [B,H,N,DH]
// One thread per (b,n,h,d<32); handles both halves of the rotation pair.
// ---------------------------------------------------------------------------
__global__ void rope_kernel(const float* __restrict__ rot)
{
    int idx = blockIdx.x * blockDim.x + threadIdx.x; // B*N*H*32 threads
    int d = idx & 31;
    int h = (idx >> 5) & (H_ - 1);
    int n = (idx >> 9) & (N_ - 1);
    int b = idx >> 20;

    const float* base = g_qkv + ((size_t)(b * N_ + n)) * (3 * INNER_) + h * DH_ + d;
    float p1 = rot[n * DH_ + d];
    float p2 = rot[n * DH_ + d + 32];
    float c1 = cosf(p1), s1 = sinf(p1);
    float c2 = cosf(p2), s2 = sinf(p2);

    size_t o = (((size_t)(b * H_ + h)) * N_ + n) * DH_ + d;

    float t1 = base[0], t2 = base[32];
    g_q[o]      = t1 * c1 - t2 * s1;
    g_q[o + 32] = t2 * c2 + t1 * s2;

    t1 = base[INNER_]; t2 = base[INNER_ + 32];
    g_k[o]      = t1 * c1 - t2 * s1;
    g_k[o + 32] = t2 * c2 + t1 * s2;

    g_v[o]      = base[2 * INNER_];
    g_v[o + 32] = base[2 * INNER_ + 32];
}

// ---------------------------------------------------------------------------
// Flash attention (fp32): one query row per thread, 128 queries per block.
// Streams K/V in 64-key shared tiles with online softmax.
// Writes g_att[b, n, h*DH + d]  (== [B,N,INNER] contiguous).
// ---------------------------------------------------------------------------
__global__ __launch_bounds__(128) void attn_kernel()
{
    const int bh = blockIdx.y;                         // 0..B*H-1
    const int qrow = blockIdx.x * 128 + threadIdx.x;   // 0..N-1
    const float* qb = g_q + (size_t)bh * N_ * DH_;
    const float* kb = g_k + (size_t)bh * N_ * DH_;
    const float* vb = g_v + (size_t)bh * N_ * DH_;

    __shared__ __align__(16) float Ksh[64][64];
    __shared__ __align__(16) float Vsh[64][64];

    float qr[64];
#pragma unroll
    for (int d = 0; d < 64; d++) qr[d] = qb[(size_t)qrow * 64 + d] * SCALE_;

    float o[64];
#pragma unroll
    for (int d = 0; d < 64; d++) o[d] = 0.f;

    float m = -1e30f, l = 0.f;

    for (int t = 0; t < N_; t += 64) {
        __syncthreads();
        const float4* ksrc = (const float4*)(kb + (size_t)t * 64);
        const float4* vsrc = (const float4*)(vb + (size_t)t * 64);
        float4* kdst = (float4*)&Ksh[0][0];
        float4* vdst = (float4*)&Vsh[0][0];
#pragma unroll
        for (int i = 0; i < 8; i++) {
            kdst[threadIdx.x + i * 128] = ksrc[threadIdx.x + i * 128];
            vdst[threadIdx.x + i * 128] = vsrc[threadIdx.x + i * 128];
        }
        __syncthreads();

        for (int j = 0; j < 64; j++) {
            const float4* kr = (const float4*)&Ksh[j][0];
            // 4 independent accumulation chains (chain length 16 not 64)
            float s0 = 0.f, s1 = 0.f, s2 = 0.f, s3 = 0.f;
#pragma unroll
            for (int c = 0; c < 16; c += 4) {
                float4 ka = kr[c], kb4 = kr[c + 1], kc = kr[c + 2], kd = kr[c + 3];
                s0 = fmaf(qr[4*c+ 0], ka.x, fmaf(qr[4*c+ 1], ka.y, fmaf(qr[4*c+ 2], ka.z, fmaf(qr[4*c+ 3], ka.w, s0))));
                s1 = fmaf(qr[4*c+ 4], kb4.x, fmaf(qr[4*c+ 5], kb4.y, fmaf(qr[4*c+ 6], kb4.z, fmaf(qr[4*c+ 7], kb4.w, s1))));
                s2 = fmaf(qr[4*c+ 8], kc.x, fmaf(qr[4*c+ 9], kc.y, fmaf(qr[4*c+10], kc.z, fmaf(qr[4*c+11], kc.w, s2))));
                s3 = fmaf(qr[4*c+12], kd.x, fmaf(qr[4*c+13], kd.y, fmaf(qr[4*c+14], kd.z, fmaf(qr[4*c+15], kd.w, s3))));
            }
            float s = (s0 + s1) + (s2 + s3);

            const float4* vr = (const float4*)&Vsh[j][0];
            if (s > m) {
                // new running max: rescale (rare after the first tiles); p == 1
                float corr = __expf(m - s);
                m = s;
                l = fmaf(l, corr, 1.f);
#pragma unroll
                for (int c = 0; c < 16; c++) {
                    float4 vv = vr[c];
                    o[4*c+0] = fmaf(o[4*c+0], corr, vv.x);
                    o[4*c+1] = fmaf(o[4*c+1], corr, vv.y);
                    o[4*c+2] = fmaf(o[4*c+2], corr, vv.z);
                    o[4*c+3] = fmaf(o[4*c+3], corr, vv.w);
                }
            } else {
                float p = __expf(s - m);
                l += p;
#pragma unroll
                for (int c = 0; c < 16; c++) {
                    float4 vv = vr[c];
                    o[4*c+0] = fmaf(p, vv.x, o[4*c+0]);
                    o[4*c+1] = fmaf(p, vv.y, o[4*c+1]);
                    o[4*c+2] = fmaf(p, vv.z, o[4*c+2]);
                    o[4*c+3] = fmaf(p, vv.w, o[4*c+3]);
                }
            }
        }
    }

    float inv = 1.f / l;
    int b = bh >> 4, h = bh & 15;
    float* ob = g_att + ((size_t)b * N_ + qrow) * INNER_ + h * DH_;
#pragma unroll
    for (int c = 0; c < 16; c++) {
        float4 w4 = make_float4(o[4*c] * inv, o[4*c+1] * inv, o[4*c+2] * inv, o[4*c+3] * inv);
        ((float4*)ob)[c] = w4;
    }
}

// ---------------------------------------------------------------------------
extern "C" void kernel_launch(void* const* d_in, const int* in_sizes, int n_in,
                              void* d_out, int out_size)
{
    (void)in_sizes; (void)n_in; (void)out_size;
    const float* x     = (const float*)d_in[0];
    const float* rot   = (const float*)d_in[1];
    const float* w_qkv = (const float*)d_in[2];
    const float* w_out = (const float*)d_in[3];
    const float* b_out = (const float*)d_in[4];
    float* out = (float*)d_out;

    float *p_qkv, *p_att;
    cudaGetSymbolAddress((void**)&p_qkv, g_qkv);
    cudaGetSymbolAddress((void**)&p_att, g_att);

    // 1) QKV projection: [B*N, DIM] x [3*INNER, DIM]^T -> [B*N, 3*INNER]
    {
        dim3 grid((3 * INNER_) / 128, (B_ * N_) / 128);
        sgemm_nt<<<grid, 256>>>(x, w_qkv, p_qkv, nullptr, B_ * N_, 3 * INNER_, DIM_);
    }
    // 2) RoPE + transpose to [B,H,N,DH]
    {
        int total = B_ * N_ * H_ * 32;
        rope_kernel<<<total / 256, 256>>>(rot);
    }
    // 3) Attention
    {
        dim3 grid(N_ / 128, B_ * H_);
        attn_kernel<<<grid, 128>>>();
    }
    // 4) Output projection + bias: [B*N, INNER] x [DIM, INNER]^T -> [B*N, DIM]
    {
        dim3 grid(DIM_ / 128, (B_ * N_) / 128);
        sgemm_nt<<<grid, 256>>>(p_att, w_out, out, b_out, B_ * N_, DIM_, INNER_);
    }
}

// round 6
// speedup vs baseline: 1.9616x; 1.9616x over previous
#include <cuda_runtime.h>
#include <cuda_bf16.h>
#include <cstdint>

#define B_ 2
#define N_ 2048
#define DIM_ 1024
#define H_ 16
#define DH_ 64
#define INNER_ 1024
#define SCALE_ 0.125f
#define KFULL_ 3072          // split GEMM K = 3 * 1024
#define NITER_ 96            // KFULL / 32

// ---------------------------------------------------------------------------
// Scratch (device globals: no cudaMalloc allowed)
// ---------------------------------------------------------------------------
__device__ float g_qkv[B_ * N_ * 3 * INNER_];   // [B,N,3*INNER]
__device__ float g_q[B_ * H_ * N_ * DH_];       // [B,H,N,DH]
__device__ float g_k[B_ * H_ * N_ * DH_];
__device__ float g_v[B_ * H_ * N_ * DH_];
__device__ float g_att[B_ * N_ * INNER_];       // [B,N,INNER]

// bf16 split buffers: A' = [hi|lo|hi], B' = [hi|hi|lo] along K (K=3072)
__device__ __nv_bfloat16 g_ax[4096 * KFULL_];   // activations (x, then att)
__device__ __nv_bfloat16 g_bq[3072 * KFULL_];   // w_qkv split
__device__ __nv_bfloat16 g_bo[1024 * KFULL_];   // w_out split

// ---------------------------------------------------------------------------
// PTX helpers (arch-portable: compile under compute_103)
// ---------------------------------------------------------------------------
__device__ __forceinline__ uint32_t smem_to_u32(const void* p) {
    uint32_t a;
    asm("{ .reg .u64 t; cvta.to.shared.u64 t, %1; cvt.u32.u64 %0, t; }" : "=r"(a) : "l"(p));
    return a;
}
__device__ __forceinline__ void cp_async16(uint32_t dst, const void* src) {
    asm volatile("cp.async.cg.shared.global [%0], [%1], 16;\n" :: "r"(dst), "l"(src));
}
#define CP_COMMIT()  asm volatile("cp.async.commit_group;\n" ::: "memory")
#define CP_WAIT2()   asm volatile("cp.async.wait_group 2;\n" ::: "memory")

#define LDMATRIX_X4(r, addr) \
    asm volatile("ldmatrix.sync.aligned.m8n8.x4.shared.b16 {%0,%1,%2,%3}, [%4];" \
        : "=r"((r)[0]), "=r"((r)[1]), "=r"((r)[2]), "=r"((r)[3]) : "r"(addr))

#define MMA16816(c, a, b0, b1) \
    asm volatile("mma.sync.aligned.m16n8k16.row.col.f32.bf16.bf16.f32 " \
        "{%0,%1,%2,%3}, {%4,%5,%6,%7}, {%8,%9}, {%0,%1,%2,%3};" \
        : "+f"((c)[0]), "+f"((c)[1]), "+f"((c)[2]), "+f"((c)[3]) \
        : "r"((a)[0]), "r"((a)[1]), "r"((a)[2]), "r"((a)[3]), "r"(b0), "r"(b1))

// ---------------------------------------------------------------------------
// fp32 -> bf16 split conversion.
// modeB=0 (activations): dst rows get [hi | lo | hi]
// modeB=1 (weights):     dst rows get [hi | hi | lo]
// Term pairing: (Ah,Bh), (Al,Bh), (Ah,Bl) — residual error ~2^-16.
// ---------------------------------------------------------------------------
__global__ void split_kernel(const float* __restrict__ src, __nv_bfloat16* __restrict__ dst,
                             int total_quads, int modeB)
{
    int i = blockIdx.x * blockDim.x + threadIdx.x;
    if (i >= total_quads) return;
    int r = i >> 8;              // / 256  (K=1024 -> 256 quads per row)
    int c = (i & 255) << 2;
    float4 v = ((const float4*)src)[i];

    __nv_bfloat16 h0 = __float2bfloat16_rn(v.x), h1 = __float2bfloat16_rn(v.y);
    __nv_bfloat16 h2 = __float2bfloat16_rn(v.z), h3 = __float2bfloat16_rn(v.w);
    __nv_bfloat16 l0 = __float2bfloat16_rn(v.x - __bfloat162float(h0));
    __nv_bfloat16 l1 = __float2bfloat16_rn(v.y - __bfloat162float(h1));
    __nv_bfloat16 l2 = __float2bfloat16_rn(v.z - __bfloat162float(h2));
    __nv_bfloat16 l3 = __float2bfloat16_rn(v.w - __bfloat162float(h3));

    __nv_bfloat162 hA = __nv_bfloat162(h0, h1), hB = __nv_bfloat162(h2, h3);
    __nv_bfloat162 lA = __nv_bfloat162(l0, l1), lB = __nv_bfloat162(l2, l3);

    size_t base = (size_t)r * KFULL_ + c;
    __nv_bfloat162* d0 = (__nv_bfloat162*)(dst + base);
    __nv_bfloat162* d1 = (__nv_bfloat162*)(dst + base + 1024);
    __nv_bfloat162* d2 = (__nv_bfloat162*)(dst + base + 2048);
    d0[0] = hA; d0[1] = hB;
    if (modeB) { d1[0] = hA; d1[1] = hB; d2[0] = lA; d2[1] = lB; }
    else       { d1[0] = lA; d1[1] = lB; d2[0] = hA; d2[1] = hB; }
}

// ---------------------------------------------------------------------------
// mma.sync bf16 NT GEMM: C[m,n] = sum_k A[m,k]*B[n,k] (+bias[n])
// A: [M, 3072], B: [Ncol, 3072] bf16 row-major. CTA tile 128x128, BK=32,
// 256 threads = 8 warps (2x4), warp tile 64x32 via m16n8k16.
// 4-stage cp.async pipeline, SMEM rows padded to 40 bf16 (80 B).
// ---------------------------------------------------------------------------
#define BK_ 32
#define ROWB_ 80                     // padded row bytes (40 bf16)
#define STAGE_ (128 * ROWB_ * 2)     // A tile + B tile = 20480 B
#define GEMM_SMEM (4 * STAGE_)       // 81920 B

__global__ __launch_bounds__(256, 2) void gemm_mma(
    const __nv_bfloat16* __restrict__ A, const __nv_bfloat16* __restrict__ Bm,
    float* __restrict__ C, const float* __restrict__ bias, int Ncol)
{
    extern __shared__ char smem_raw[];
    const uint32_t sb = smem_to_u32(smem_raw);

    const int tid = threadIdx.x;
    const int lane = tid & 31, wid = tid >> 5;
    const int bm = blockIdx.y * 128, bn = blockIdx.x * 128;
    const int wm = (wid >> 2) * 64, wn = (wid & 3) * 32;

    const __nv_bfloat16* Abase = A + (size_t)bm * KFULL_;
    const __nv_bfloat16* Bbase = Bm + (size_t)bn * KFULL_;

    // loader: thread -> (row, 32B half of the 64B k-chunk)
    const int lrow = tid >> 1;
    const int lhalfB = (tid & 1) * 32;          // byte offset in smem row
    const int lhalfE = (tid & 1) * 16;          // element offset in gmem row
    const uint32_t so = (uint32_t)(lrow * ROWB_ + lhalfB);

    // ldmatrix offsets (within a stage)
    // A: row = wm + mi*16 + (lane&15), kbyte = (lane>>4)*16 (+ kstep*32)
    const uint32_t a_off = (uint32_t)((wm + (lane & 15)) * ROWB_ + (lane >> 4) * 16);
    // B: n_row = wn + nb*16 + ((lane>>4)<<3) + (lane&7), kbyte = ((lane>>3)&1)*16
    const uint32_t b_off = (uint32_t)((wn + ((lane >> 4) << 3) + (lane & 7)) * ROWB_
                                      + ((lane >> 3) & 1) * 16);

    float acc[4][4][4];
#pragma unroll
    for (int mi = 0; mi < 4; mi++)
#pragma unroll
        for (int ni = 0; ni < 4; ni++)
#pragma unroll
            for (int r = 0; r < 4; r++) acc[mi][ni][r] = 0.f;

    auto load_tile = [&](int it) {
        uint32_t sa = sb + (uint32_t)(it & 3) * STAGE_;
        uint32_t sbb = sa + 128 * ROWB_;
        const __nv_bfloat16* Ag = Abase + (size_t)lrow * KFULL_ + it * BK_ + lhalfE;
        const __nv_bfloat16* Bg = Bbase + (size_t)lrow * KFULL_ + it * BK_ + lhalfE;
        cp_async16(sa + so, Ag);
        cp_async16(sa + so + 16, Ag + 8);
        cp_async16(sbb + so, Bg);
        cp_async16(sbb + so + 16, Bg + 8);
        CP_COMMIT();
    };

    load_tile(0);
    load_tile(1);
    load_tile(2);

    for (int it = 0; it < NITER_; it++) {
        CP_WAIT2();            // stage it&3 landed
        __syncthreads();       // visible to all; all finished compute(it-1)
        if (it + 3 < NITER_) load_tile(it + 3);   // -> stage (it-1)&3, safe past barrier

        uint32_t sa = sb + (uint32_t)(it & 3) * STAGE_;
        uint32_t sbb = sa + 128 * ROWB_;
#pragma unroll
        for (int ks = 0; ks < 2; ks++) {
            uint32_t af[4][4], bf[2][4];
#pragma unroll
            for (int mi = 0; mi < 4; mi++)
                LDMATRIX_X4(af[mi], sa + a_off + mi * (16 * ROWB_) + ks * 32);
#pragma unroll
            for (int nb = 0; nb < 2; nb++)
                LDMATRIX_X4(bf[nb], sbb + b_off + nb * (16 * ROWB_) + ks * 32);
#pragma unroll
            for (int mi = 0; mi < 4; mi++)
#pragma unroll
                for (int ni = 0; ni < 4; ni++)
                    MMA16816(acc[mi][ni], af[mi], bf[ni >> 1][(ni & 1) * 2],
                             bf[ni >> 1][(ni & 1) * 2 + 1]);
        }
    }

    // Epilogue: c0,c1 -> (row, col..col+1); c2,c3 -> (row+8, ...)
#pragma unroll
    for (int mi = 0; mi < 4; mi++) {
        int row = bm + wm + mi * 16 + (lane >> 2);
#pragma unroll
        for (int ni = 0; ni < 4; ni++) {
            int col = bn + wn + ni * 8 + (lane & 3) * 2;
            float b0 = 0.f, b1 = 0.f;
            if (bias) { b0 = bias[col]; b1 = bias[col + 1]; }
            float2 v0 = make_float2(acc[mi][ni][0] + b0, acc[mi][ni][1] + b1);
            float2 v1 = make_float2(acc[mi][ni][2] + b0, acc[mi][ni][3] + b1);
            *(float2*)(C + (size_t)row * Ncol + col) = v0;
            *(float2*)(C + (size_t)(row + 8) * Ncol + col) = v1;
        }
    }
}

// ---------------------------------------------------------------------------
// RoPE + reshape [B,N,3*INNER] -> q,k (rotary applied), v in [B,H,N,DH]
// ---------------------------------------------------------------------------
__global__ void rope_kernel(const float* __restrict__ rot)
{
    int idx = blockIdx.x * blockDim.x + threadIdx.x; // B*N*H*32 threads
    int d = idx & 31;
    int h = (idx >> 5) & (H_ - 1);
    int n = (idx >> 9) & (N_ - 1);
    int b = idx >> 20;

    const float* base = g_qkv + ((size_t)(b * N_ + n)) * (3 * INNER_) + h * DH_ + d;
    float p1 = rot[n * DH_ + d];
    float p2 = rot[n * DH_ + d + 32];
    float c1 = cosf(p1), s1 = sinf(p1);
    float c2 = cosf(p2), s2 = sinf(p2);

    size_t o = (((size_t)(b * H_ + h)) * N_ + n) * DH_ + d;

    float t1 = base[0], t2 = base[32];
    g_q[o]      = t1 * c1 - t2 * s1;
    g_q[o + 32] = t2 * c2 + t1 * s2;

    t1 = base[INNER_]; t2 = base[INNER_ + 32];
    g_k[o]      = t1 * c1 - t2 * s1;
    g_k[o + 32] = t2 * c2 + t1 * s2;

    g_v[o]      = base[2 * INNER_];
    g_v[o + 32] = base[2 * INNER_ + 32];
}

// ---------------------------------------------------------------------------
// Flash attention (fp32): one query row per thread, 128 queries per block.
// ---------------------------------------------------------------------------
__global__ __launch_bounds__(128) void attn_kernel()
{
    const int bh = blockIdx.y;
    const int qrow = blockIdx.x * 128 + threadIdx.x;
    const float* qb = g_q + (size_t)bh * N_ * DH_;
    const float* kb = g_k + (size_t)bh * N_ * DH_;
    const float* vb = g_v + (size_t)bh * N_ * DH_;

    __shared__ __align__(16) float Ksh[64][64];
    __shared__ __align__(16) float Vsh[64][64];

    float qr[64];
#pragma unroll
    for (int d = 0; d < 64; d++) qr[d] = qb[(size_t)qrow * 64 + d] * SCALE_;

    float o[64];
#pragma unroll
    for (int d = 0; d < 64; d++) o[d] = 0.f;

    float m = -1e30f, l = 0.f;

    for (int t = 0; t < N_; t += 64) {
        __syncthreads();
        const float4* ksrc = (const float4*)(kb + (size_t)t * 64);
        const float4* vsrc = (const float4*)(vb + (size_t)t * 64);
        float4* kdst = (float4*)&Ksh[0][0];
        float4* vdst = (float4*)&Vsh[0][0];
#pragma unroll
        for (int i = 0; i < 8; i++) {
            kdst[threadIdx.x + i * 128] = ksrc[threadIdx.x + i * 128];
            vdst[threadIdx.x + i * 128] = vsrc[threadIdx.x + i * 128];
        }
        __syncthreads();

        for (int j = 0; j < 64; j++) {
            const float4* kr = (const float4*)&Ksh[j][0];
            float s0 = 0.f, s1 = 0.f, s2 = 0.f, s3 = 0.f;
#pragma unroll
            for (int c = 0; c < 16; c += 4) {
                float4 ka = kr[c], kb4 = kr[c + 1], kc = kr[c + 2], kd = kr[c + 3];
                s0 = fmaf(qr[4*c+ 0], ka.x, fmaf(qr[4*c+ 1], ka.y, fmaf(qr[4*c+ 2], ka.z, fmaf(qr[4*c+ 3], ka.w, s0))));
                s1 = fmaf(qr[4*c+ 4], kb4.x, fmaf(qr[4*c+ 5], kb4.y, fmaf(qr[4*c+ 6], kb4.z, fmaf(qr[4*c+ 7], kb4.w, s1))));
                s2 = fmaf(qr[4*c+ 8], kc.x, fmaf(qr[4*c+ 9], kc.y, fmaf(qr[4*c+10], kc.z, fmaf(qr[4*c+11], kc.w, s2))));
                s3 = fmaf(qr[4*c+12], kd.x, fmaf(qr[4*c+13], kd.y, fmaf(qr[4*c+14], kd.z, fmaf(qr[4*c+15], kd.w, s3))));
            }
            float s = (s0 + s1) + (s2 + s3);

            const float4* vr = (const float4*)&Vsh[j][0];
            if (s > m) {
                float corr = __expf(m - s);
                m = s;
                l = fmaf(l, corr, 1.f);
#pragma unroll
                for (int c = 0; c < 16; c++) {
                    float4 vv = vr[c];
                    o[4*c+0] = fmaf(o[4*c+0], corr, vv.x);
                    o[4*c+1] = fmaf(o[4*c+1], corr, vv.y);
                    o[4*c+2] = fmaf(o[4*c+2], corr, vv.z);
                    o[4*c+3] = fmaf(o[4*c+3], corr, vv.w);
                }
            } else {
                float p = __expf(s - m);
                l += p;
#pragma unroll
                for (int c = 0; c < 16; c++) {
                    float4 vv = vr[c];
                    o[4*c+0] = fmaf(p, vv.x, o[4*c+0]);
                    o[4*c+1] = fmaf(p, vv.y, o[4*c+1]);
                    o[4*c+2] = fmaf(p, vv.z, o[4*c+2]);
                    o[4*c+3] = fmaf(p, vv.w, o[4*c+3]);
                }
            }
        }
    }

    float inv = 1.f / l;
    int b = bh >> 4, h = bh & 15;
    float* ob = g_att + ((size_t)b * N_ + qrow) * INNER_ + h * DH_;
#pragma unroll
    for (int c = 0; c < 16; c++) {
        float4 w4 = make_float4(o[4*c] * inv, o[4*c+1] * inv, o[4*c+2] * inv, o[4*c+3] * inv);
        ((float4*)ob)[c] = w4;
    }
}

// ---------------------------------------------------------------------------
extern "C" void kernel_launch(void* const* d_in, const int* in_sizes, int n_in,
                              void* d_out, int out_size)
{
    (void)in_sizes; (void)n_in; (void)out_size;
    const float* x     = (const float*)d_in[0];
    const float* rot   = (const float*)d_in[1];
    const float* w_qkv = (const float*)d_in[2];
    const float* w_out = (const float*)d_in[3];
    const float* b_out = (const float*)d_in[4];
    float* out = (float*)d_out;

    float *p_qkv, *p_att;
    __nv_bfloat16 *p_ax, *p_bq, *p_bo;
    cudaGetSymbolAddress((void**)&p_qkv, g_qkv);
    cudaGetSymbolAddress((void**)&p_att, g_att);
    cudaGetSymbolAddress((void**)&p_ax, g_ax);
    cudaGetSymbolAddress((void**)&p_bq, g_bq);
    cudaGetSymbolAddress((void**)&p_bo, g_bo);

    cudaFuncSetAttribute(gemm_mma, cudaFuncAttributeMaxDynamicSharedMemorySize, GEMM_SMEM);

    // 1) split x -> A' [4096, 3072], w_qkv -> B' [3072, 3072]
    split_kernel<<<(4096 * 256) / 256, 256>>>(x, p_ax, 4096 * 256, 0);
    split_kernel<<<(3072 * 256) / 256, 256>>>(w_qkv, p_bq, 3072 * 256, 1);

    // 2) QKV projection (tensor cores, fp32 accuracy via 3-term split)
    {
        dim3 grid(3072 / 128, 4096 / 128);
        gemm_mma<<<grid, 256, GEMM_SMEM>>>(p_ax, p_bq, p_qkv, nullptr, 3072);
    }

    // 3) RoPE + transpose to [B,H,N,DH]
    rope_kernel<<<(B_ * N_ * H_ * 32) / 256, 256>>>(rot);

    // 4) Attention (fp32)
    {
        dim3 grid(N_ / 128, B_ * H_);
        attn_kernel<<<grid, 128>>>();
    }

    // 5) split att -> A', w_out -> B' [1024, 3072]
    split_kernel<<<(4096 * 256) / 256, 256>>>(p_att, p_ax, 4096 * 256, 0);
    split_kernel<<<(1024 * 256) / 256, 256>>>(w_out, p_bo, 1024 * 256, 1);

    // 6) Output projection + bias (tensor cores)
    {
        dim3 grid(1024 / 128, 4096 / 128);
        gemm_mma<<<grid, 256, GEMM_SMEM>>>(p_ax, p_bo, out, b_out, 1024);
    }
}

// round 8
// speedup vs baseline: 4.7616x; 2.4274x over previous
#include <cuda_runtime.h>
#include <cuda_bf16.h>
#include <cstdint>

#define B_ 2
#define N_ 2048
#define DIM_ 1024
#define H_ 16
#define DH_ 64
#define INNER_ 1024
#define SCALE_ 0.125f
#define KFULL_ 3072          // split GEMM K = 3 * 1024
#define NITER_ 96            // KFULL / 32

// ---------------------------------------------------------------------------
// Scratch (device globals: no cudaMalloc allowed)
// ---------------------------------------------------------------------------
__device__ float g_qkv[B_ * N_ * 3 * INNER_];   // [B,N,3*INNER]
__device__ float g_att[B_ * N_ * INNER_];       // [B,N,INNER]

// attention operands, pre-split bf16
__device__ __nv_bfloat16 g_qs[32 * N_ * 192];   // [bh][n][qh|ql|qh] (scaled)
__device__ __nv_bfloat16 g_ks[32 * N_ * 192];   // [bh][n][kh|kh|kl]
__device__ __nv_bfloat16 g_vh[32 * N_ * 64];
__device__ __nv_bfloat16 g_vl[32 * N_ * 64];

// bf16 split buffers for projection GEMMs
__device__ __nv_bfloat16 g_ax[4096 * KFULL_];   // activations (x, then att)
__device__ __nv_bfloat16 g_bq[3072 * KFULL_];   // w_qkv split
__device__ __nv_bfloat16 g_bo[1024 * KFULL_];   // w_out split

// ---------------------------------------------------------------------------
// PTX helpers (arch-portable: compile under compute_103)
// ---------------------------------------------------------------------------
__device__ __forceinline__ uint32_t smem_to_u32(const void* p) {
    uint32_t a;
    asm("{ .reg .u64 t; cvta.to.shared.u64 t, %1; cvt.u32.u64 %0, t; }" : "=r"(a) : "l"(p));
    return a;
}
__device__ __forceinline__ void cp_async16(uint32_t dst, const void* src) {
    asm volatile("cp.async.cg.shared.global [%0], [%1], 16;\n" :: "r"(dst), "l"(src));
}
#define CP_COMMIT()  asm volatile("cp.async.commit_group;\n" ::: "memory")
#define CP_WAIT2()   asm volatile("cp.async.wait_group 2;\n" ::: "memory")
#define CP_WAIT1()   asm volatile("cp.async.wait_group 1;\n" ::: "memory")
#define CP_WAIT0()   asm volatile("cp.async.wait_group 0;\n" ::: "memory")

#define LDMATRIX_X4(r, addr) \
    asm volatile("ldmatrix.sync.aligned.m8n8.x4.shared.b16 {%0,%1,%2,%3}, [%4];" \
        : "=r"((r)[0]), "=r"((r)[1]), "=r"((r)[2]), "=r"((r)[3]) : "r"(addr))

#define LDMATRIX_X4_T(r, addr) \
    asm volatile("ldmatrix.sync.aligned.m8n8.x4.trans.shared.b16 {%0,%1,%2,%3}, [%4];" \
        : "=r"((r)[0]), "=r"((r)[1]), "=r"((r)[2]), "=r"((r)[3]) : "r"(addr))

#define MMA16816(c, a, b0, b1) \
    asm volatile("mma.sync.aligned.m16n8k16.row.col.f32.bf16.bf16.f32 " \
        "{%0,%1,%2,%3}, {%4,%5,%6,%7}, {%8,%9}, {%0,%1,%2,%3};" \
        : "+f"((c)[0]), "+f"((c)[1]), "+f"((c)[2]), "+f"((c)[3]) \
        : "r"((a)[0]), "r"((a)[1]), "r"((a)[2]), "r"((a)[3]), "r"(b0), "r"(b1))

// pack bf16x2 from two fp32 (lo -> low half, hi -> high half), round-nearest
#define PACK_BF16X2_RN(d, lo, hi) \
    asm("cvt.rn.bf16x2.f32 %0, %1, %2;" : "=r"(d) : "f"(hi), "f"(lo))

// ---------------------------------------------------------------------------
// fp32 -> bf16 split conversion for projection GEMMs.
// modeB=0 (activations): dst rows get [hi | lo | hi]
// modeB=1 (weights):     dst rows get [hi | hi | lo]
// ---------------------------------------------------------------------------
__global__ void split_kernel(const float* __restrict__ src, __nv_bfloat16* __restrict__ dst,
                             int total_quads, int modeB)
{
    int i = blockIdx.x * blockDim.x + threadIdx.x;
    if (i >= total_quads) return;
    int r = i >> 8;              // / 256  (K=1024 -> 256 quads per row)
    int c = (i & 255) << 2;
    float4 v = ((const float4*)src)[i];

    __nv_bfloat16 h0 = __float2bfloat16_rn(v.x), h1 = __float2bfloat16_rn(v.y);
    __nv_bfloat16 h2 = __float2bfloat16_rn(v.z), h3 = __float2bfloat16_rn(v.w);
    __nv_bfloat16 l0 = __float2bfloat16_rn(v.x - __bfloat162float(h0));
    __nv_bfloat16 l1 = __float2bfloat16_rn(v.y - __bfloat162float(h1));
    __nv_bfloat16 l2 = __float2bfloat16_rn(v.z - __bfloat162float(h2));
    __nv_bfloat16 l3 = __float2bfloat16_rn(v.w - __bfloat162float(h3));

    __nv_bfloat162 hA = __nv_bfloat162(h0, h1), hB = __nv_bfloat162(h2, h3);
    __nv_bfloat162 lA = __nv_bfloat162(l0, l1), lB = __nv_bfloat162(l2, l3);

    size_t base = (size_t)r * KFULL_ + c;
    __nv_bfloat162* d0 = (__nv_bfloat162*)(dst + base);
    __nv_bfloat162* d1 = (__nv_bfloat162*)(dst + base + 1024);
    __nv_bfloat162* d2 = (__nv_bfloat162*)(dst + base + 2048);
    d0[0] = hA; d0[1] = hB;
    if (modeB) { d1[0] = hA; d1[1] = hB; d2[0] = lA; d2[1] = lB; }
    else       { d1[0] = lA; d1[1] = lB; d2[0] = hA; d2[1] = hB; }
}

// ---------------------------------------------------------------------------
// mma.sync bf16 NT GEMM (unchanged from R6): C[m,n] = sum_k A[m,k]*B[n,k] (+bias)
// ---------------------------------------------------------------------------
#define BK_ 32
#define ROWB_ 80
#define STAGE_ (128 * ROWB_ * 2)
#define GEMM_SMEM (4 * STAGE_)

__global__ __launch_bounds__(256, 2) void gemm_mma(
    const __nv_bfloat16* __restrict__ A, const __nv_bfloat16* __restrict__ Bm,
    float* __restrict__ C, const float* __restrict__ bias, int Ncol)
{
    extern __shared__ char smem_raw[];
    const uint32_t sb = smem_to_u32(smem_raw);

    const int tid = threadIdx.x;
    const int lane = tid & 31, wid = tid >> 5;
    const int bm = blockIdx.y * 128, bn = blockIdx.x * 128;
    const int wm = (wid >> 2) * 64, wn = (wid & 3) * 32;

    const __nv_bfloat16* Abase = A + (size_t)bm * KFULL_;
    const __nv_bfloat16* Bbase = Bm + (size_t)bn * KFULL_;

    const int lrow = tid >> 1;
    const int lhalfB = (tid & 1) * 32;
    const int lhalfE = (tid & 1) * 16;
    const uint32_t so = (uint32_t)(lrow * ROWB_ + lhalfB);

    const uint32_t a_off = (uint32_t)((wm + (lane & 15)) * ROWB_ + (lane >> 4) * 16);
    const uint32_t b_off = (uint32_t)((wn + ((lane >> 4) << 3) + (lane & 7)) * ROWB_
                                      + ((lane >> 3) & 1) * 16);

    float acc[4][4][4];
#pragma unroll
    for (int mi = 0; mi < 4; mi++)
#pragma unroll
        for (int ni = 0; ni < 4; ni++)
#pragma unroll
            for (int r = 0; r < 4; r++) acc[mi][ni][r] = 0.f;

    auto load_tile = [&](int it) {
        uint32_t sa = sb + (uint32_t)(it & 3) * STAGE_;
        uint32_t sbb = sa + 128 * ROWB_;
        const __nv_bfloat16* Ag = Abase + (size_t)lrow * KFULL_ + it * BK_ + lhalfE;
        const __nv_bfloat16* Bg = Bbase + (size_t)lrow * KFULL_ + it * BK_ + lhalfE;
        cp_async16(sa + so, Ag);
        cp_async16(sa + so + 16, Ag + 8);
        cp_async16(sbb + so, Bg);
        cp_async16(sbb + so + 16, Bg + 8);
        CP_COMMIT();
    };

    load_tile(0);
    load_tile(1);
    load_tile(2);

    for (int it = 0; it < NITER_; it++) {
        CP_WAIT2();
        __syncthreads();
        if (it + 3 < NITER_) load_tile(it + 3);

        uint32_t sa = sb + (uint32_t)(it & 3) * STAGE_;
        uint32_t sbb = sa + 128 * ROWB_;
#pragma unroll
        for (int ks = 0; ks < 2; ks++) {
            uint32_t af[4][4], bf[2][4];
#pragma unroll
            for (int mi = 0; mi < 4; mi++)
                LDMATRIX_X4(af[mi], sa + a_off + mi * (16 * ROWB_) + ks * 32);
#pragma unroll
            for (int nb = 0; nb < 2; nb++)
                LDMATRIX_X4(bf[nb], sbb + b_off + nb * (16 * ROWB_) + ks * 32);
#pragma unroll
            for (int mi = 0; mi < 4; mi++)
#pragma unroll
                for (int ni = 0; ni < 4; ni++)
                    MMA16816(acc[mi][ni], af[mi], bf[ni >> 1][(ni & 1) * 2],
                             bf[ni >> 1][(ni & 1) * 2 + 1]);
        }
    }

#pragma unroll
    for (int mi = 0; mi < 4; mi++) {
        int row = bm + wm + mi * 16 + (lane >> 2);
#pragma unroll
        for (int ni = 0; ni < 4; ni++) {
            int col = bn + wn + ni * 8 + (lane & 3) * 2;
            float b0 = 0.f, b1 = 0.f;
            if (bias) { b0 = bias[col]; b1 = bias[col + 1]; }
            float2 v0 = make_float2(acc[mi][ni][0] + b0, acc[mi][ni][1] + b1);
            float2 v1 = make_float2(acc[mi][ni][2] + b0, acc[mi][ni][3] + b1);
            *(float2*)(C + (size_t)row * Ncol + col) = v0;
            *(float2*)(C + (size_t)(row + 8) * Ncol + col) = v1;
        }
    }
}

// ---------------------------------------------------------------------------
// RoPE + split: g_qkv -> g_qs [qh|ql|qh]*SCALE, g_ks [kh|kh|kl], g_vh, g_vl
// One thread per (bh, n, d<32); handles rotation pair (d, d+32).
// ---------------------------------------------------------------------------
__device__ __forceinline__ void split2(float x, __nv_bfloat16& hi, __nv_bfloat16& lo) {
    hi = __float2bfloat16_rn(x);
    lo = __float2bfloat16_rn(x - __bfloat162float(hi));
}

__global__ void rope_split_kernel(const float* __restrict__ rot)
{
    int idx = blockIdx.x * blockDim.x + threadIdx.x;  // 32*2048*32 threads
    int d = idx & 31;
    int n = (idx >> 5) & (N_ - 1);
    int bh = idx >> 16;
    int b = bh >> 4, h = bh & 15;

    const float* base = g_qkv + ((size_t)(b * N_ + n)) * (3 * INNER_) + h * DH_ + d;
    float p1 = rot[n * DH_ + d];
    float p2 = rot[n * DH_ + d + 32];
    float c1 = cosf(p1), s1 = sinf(p1);
    float c2 = cosf(p2), s2 = sinf(p2);

    float q1 = base[0], q2 = base[32];
    float k1 = base[INNER_], k2 = base[INNER_ + 32];
    float v1 = base[2 * INNER_], v2 = base[2 * INNER_ + 32];

    float qr1 = (q1 * c1 - q2 * s1) * SCALE_;
    float qr2 = (q2 * c2 + q1 * s2) * SCALE_;
    float kr1 = k1 * c1 - k2 * s1;
    float kr2 = k2 * c2 + k1 * s2;

    __nv_bfloat16 qh1, ql1, qh2, ql2, kh1, kl1, kh2, kl2, vh1, vl1, vh2, vl2;
    split2(qr1, qh1, ql1); split2(qr2, qh2, ql2);
    split2(kr1, kh1, kl1); split2(kr2, kh2, kl2);
    split2(v1, vh1, vl1);  split2(v2, vh2, vl2);

    size_t qb = ((size_t)bh * N_ + n) * 192 + d;
    g_qs[qb]       = qh1; g_qs[qb + 32]       = qh2;
    g_qs[qb + 64]  = ql1; g_qs[qb + 96]       = ql2;
    g_qs[qb + 128] = qh1; g_qs[qb + 160]      = qh2;
    g_ks[qb]       = kh1; g_ks[qb + 32]       = kh2;
    g_ks[qb + 64]  = kh1; g_ks[qb + 96]       = kh2;
    g_ks[qb + 128] = kl1; g_ks[qb + 160]      = kl2;

    size_t vb = ((size_t)bh * N_ + n) * 64 + d;
    g_vh[vb] = vh1; g_vh[vb + 32] = vh2;
    g_vl[vb] = vl1; g_vl[vb + 32] = vl2;
}

// ---------------------------------------------------------------------------
// Tensor-core flash attention.
// CTA: 128 q-rows (8 warps x 16), key tiles of 64, double-buffered cp.async.
// S = Q'K'^T (3-term split, K=192). Online softmax in fp32 c-frags.
// O += Ph*Vh + Pl*Vh + Ph*Vl (P split in registers).
// ---------------------------------------------------------------------------
#define KT_ 64                   // keys per tile
#define NT_ (N_ / KT_)           // 32 tiles
#define KROWB_ 400               // 192 bf16 + 8 pad = 200 el
#define VROWB_ 144               // 64 bf16 + 8 pad = 72 el
#define QS_BYTES (128 * KROWB_)              // 51200
#define AST_BYTES (KT_ * KROWB_ + 2 * KT_ * VROWB_)  // 25600+18432 = 44032
#define ATTN_SMEM (QS_BYTES + 2 * AST_BYTES)         // 139264

__global__ __launch_bounds__(256, 1) void attn_mma()
{
    extern __shared__ char smem_raw[];
    const uint32_t sb = smem_to_u32(smem_raw);
    const uint32_t QS = sb;

    const int tid = threadIdx.x;
    const int lane = tid & 31, wid = tid >> 5;
    const int qt = blockIdx.x;       // q tile (16)
    const int bh = blockIdx.y;       // 32
    const int b = bh >> 4, h = bh & 15;

    const __nv_bfloat16* Qg = g_qs + ((size_t)bh * N_ + qt * 128) * 192;
    const __nv_bfloat16* Kg = g_ks + (size_t)bh * N_ * 192;
    const __nv_bfloat16* Vhg = g_vh + (size_t)bh * N_ * 64;
    const __nv_bfloat16* Vlg = g_vl + (size_t)bh * N_ * 64;

    // ---- async load Q tile (group 0) ----
#pragma unroll
    for (int j = 0; j < 12; j++) {
        int idx = tid + j * 256;          // 3072 chunks
        int row = idx / 24, c = idx % 24;
        cp_async16(QS + row * KROWB_ + c * 16, Qg + (size_t)row * 192 + c * 8);
    }
    CP_COMMIT();

    auto load_tile = [&](int t) {
        uint32_t st = sb + QS_BYTES + (uint32_t)(t & 1) * AST_BYTES;
        uint32_t vh_st = st + KT_ * KROWB_;
        uint32_t vl_st = vh_st + KT_ * VROWB_;
        int kb = t * KT_;
#pragma unroll
        for (int j = 0; j < 6; j++) {
            int idx = tid + j * 256;      // 1536 chunks
            int row = idx / 24, c = idx % 24;
            cp_async16(st + row * KROWB_ + c * 16, Kg + (size_t)(kb + row) * 192 + c * 8);
        }
#pragma unroll
        for (int j = 0; j < 2; j++) {
            int idx = tid + j * 256;      // 512 chunks
            int row = idx >> 3, c = idx & 7;
            cp_async16(vh_st + row * VROWB_ + c * 16, Vhg + (size_t)(kb + row) * 64 + c * 8);
            cp_async16(vl_st + row * VROWB_ + c * 16, Vlg + (size_t)(kb + row) * 64 + c * 8);
        }
        CP_COMMIT();
    };

    load_tile(0);
    CP_WAIT1();                 // Q landed
    __syncthreads();

    // ---- extract Q fragments: 12 k-steps x 4 regs ----
    uint32_t af[12][4];
    {
        uint32_t a_off = QS + (uint32_t)((wid * 16 + (lane & 15)) * KROWB_ + (lane >> 4) * 16);
#pragma unroll
        for (int ks = 0; ks < 12; ks++)
            LDMATRIX_X4(af[ks], a_off + ks * 32);
    }

    float O[8][4];
#pragma unroll
    for (int g = 0; g < 8; g++)
#pragma unroll
        for (int r = 0; r < 4; r++) O[g][r] = 0.f;
    float m0 = -1e30f, m1 = -1e30f, l0 = 0.f, l1 = 0.f;

    const uint32_t kb_off = (uint32_t)((((lane >> 4) << 3) + (lane & 7)) * KROWB_
                                       + ((lane >> 3) & 1) * 16);
    const uint32_t v_off = (uint32_t)((((lane >> 3) & 1) * 8 + (lane & 7)) * VROWB_
                                      + ((lane >> 4) << 3) * 2);

    for (int t = 0; t < NT_; t++) {
        if (t + 1 < NT_) load_tile(t + 1);
        if (t + 1 < NT_) { CP_WAIT1(); } else { CP_WAIT0(); }
        __syncthreads();

        uint32_t st = sb + QS_BYTES + (uint32_t)(t & 1) * AST_BYTES;
        uint32_t vh_st = st + KT_ * KROWB_;
        uint32_t vl_st = vh_st + KT_ * VROWB_;

        // ---- S = Q'K'^T : 8 key-blocks x 12 k-steps ----
        float S[8][4];
#pragma unroll
        for (int g = 0; g < 8; g++)
#pragma unroll
            for (int r = 0; r < 4; r++) S[g][r] = 0.f;

#pragma unroll
        for (int ks = 0; ks < 12; ks++) {
            uint32_t kf[4][4];
#pragma unroll
            for (int g = 0; g < 4; g++)
                LDMATRIX_X4(kf[g], st + kb_off + g * (16 * KROWB_) + ks * 32);
#pragma unroll
            for (int g = 0; g < 4; g++) {
                MMA16816(S[2 * g],     af[ks], kf[g][0], kf[g][1]);
                MMA16816(S[2 * g + 1], af[ks], kf[g][2], kf[g][3]);
            }
        }

        // ---- online softmax ----
        float mx0 = -1e30f, mx1 = -1e30f;
#pragma unroll
        for (int g = 0; g < 8; g++) {
            mx0 = fmaxf(mx0, fmaxf(S[g][0], S[g][1]));
            mx1 = fmaxf(mx1, fmaxf(S[g][2], S[g][3]));
        }
        mx0 = fmaxf(mx0, __shfl_xor_sync(0xffffffffu, mx0, 1));
        mx0 = fmaxf(mx0, __shfl_xor_sync(0xffffffffu, mx0, 2));
        mx1 = fmaxf(mx1, __shfl_xor_sync(0xffffffffu, mx1, 1));
        mx1 = fmaxf(mx1, __shfl_xor_sync(0xffffffffu, mx1, 2));

        float m0n = fmaxf(m0, mx0), m1n = fmaxf(m1, mx1);
        float corr0 = __expf(m0 - m0n), corr1 = __expf(m1 - m1n);
        m0 = m0n; m1 = m1n;
        l0 *= corr0; l1 *= corr1;

#pragma unroll
        for (int g = 0; g < 8; g++) {
            S[g][0] = __expf(S[g][0] - m0);
            S[g][1] = __expf(S[g][1] - m0);
            S[g][2] = __expf(S[g][2] - m1);
            S[g][3] = __expf(S[g][3] - m1);
            l0 += S[g][0] + S[g][1];
            l1 += S[g][2] + S[g][3];
            O[g][0] *= corr0; O[g][1] *= corr0;
            O[g][2] *= corr1; O[g][3] *= corr1;
        }

        // ---- O += P * V (3-term split) : 4 k-steps over keys ----
#pragma unroll
        for (int ks = 0; ks < 4; ks++) {
            // P a-frags from S blocks 2ks, 2ks+1: hi via bf16-truncation, lo residual
            uint32_t ph[4], pl[4];
#pragma unroll
            for (int half = 0; half < 2; half++) {       // S block 2ks+half -> regs 2half..
                const float* Sp = S[2 * ks + half];
#pragma unroll
                for (int pr = 0; pr < 2; pr++) {         // (c0,c1) then (c2,c3)
                    float pa = Sp[2 * pr], pb = Sp[2 * pr + 1];
                    uint32_t ua = __float_as_uint(pa), ub = __float_as_uint(pb);
                    ph[2 * half + pr] = __byte_perm(ua, ub, 0x7632);   // truncated hi pair
                    float ra = pa - __uint_as_float(ua & 0xffff0000u);
                    float rb = pb - __uint_as_float(ub & 0xffff0000u);
                    PACK_BF16X2_RN(pl[2 * half + pr], ra, rb);
                }
            }
            uint32_t vh[4][4], vl[4][4];
#pragma unroll
            for (int g = 0; g < 4; g++) {
                LDMATRIX_X4_T(vh[g], vh_st + v_off + ks * (16 * VROWB_) + g * 32);
                LDMATRIX_X4_T(vl[g], vl_st + v_off + ks * (16 * VROWB_) + g * 32);
            }
#pragma unroll
            for (int g = 0; g < 4; g++) {
                MMA16816(O[2 * g],     ph, vh[g][0], vh[g][1]);
                MMA16816(O[2 * g + 1], ph, vh[g][2], vh[g][3]);
                MMA16816(O[2 * g],     pl, vh[g][0], vh[g][1]);
                MMA16816(O[2 * g + 1], pl, vh[g][2], vh[g][3]);
                MMA16816(O[2 * g],     ph, vl[g][0], vl[g][1]);
                MMA16816(O[2 * g + 1], ph, vl[g][2], vl[g][3]);
            }
        }
        __syncthreads();
    }

    // ---- finalize: reduce l over quad lanes, scale, store ----
    l0 += __shfl_xor_sync(0xffffffffu, l0, 1);
    l0 += __shfl_xor_sync(0xffffffffu, l0, 2);
    l1 += __shfl_xor_sync(0xffffffffu, l1, 1);
    l1 += __shfl_xor_sync(0xffffffffu, l1, 2);
    float inv0 = 1.f / l0, inv1 = 1.f / l1;

    int row = qt * 128 + wid * 16 + (lane >> 2);
    float* ob = g_att + ((size_t)b * N_ + row) * INNER_ + h * DH_ + (lane & 3) * 2;
#pragma unroll
    for (int g = 0; g < 8; g++) {
        *(float2*)(ob + g * 8) = make_float2(O[g][0] * inv0, O[g][1] * inv0);
        *(float2*)(ob + 8 * INNER_ + g * 8) = make_float2(O[g][2] * inv1, O[g][3] * inv1);
    }
}

// ---------------------------------------------------------------------------
extern "C" void kernel_launch(void* const* d_in, const int* in_sizes, int n_in,
                              void* d_out, int out_size)
{
    (void)in_sizes; (void)n_in; (void)out_size;
    const float* x     = (const float*)d_in[0];
    const float* rot   = (const float*)d_in[1];
    const float* w_qkv = (const float*)d_in[2];
    const float* w_out = (const float*)d_in[3];
    const float* b_out = (const float*)d_in[4];
    float* out = (float*)d_out;

    float *p_qkv, *p_att;
    __nv_bfloat16 *p_ax, *p_bq, *p_bo;
    cudaGetSymbolAddress((void**)&p_qkv, g_qkv);
    cudaGetSymbolAddress((void**)&p_att, g_att);
    cudaGetSymbolAddress((void**)&p_ax, g_ax);
    cudaGetSymbolAddress((void**)&p_bq, g_bq);
    cudaGetSymbolAddress((void**)&p_bo, g_bo);

    cudaFuncSetAttribute(gemm_mma, cudaFuncAttributeMaxDynamicSharedMemorySize, GEMM_SMEM);
    cudaFuncSetAttribute(attn_mma, cudaFuncAttributeMaxDynamicSharedMemorySize, ATTN_SMEM);

    // 1) split x -> A' [4096, 3072], w_qkv -> B' [3072, 3072]
    split_kernel<<<(4096 * 256) / 256, 256>>>(x, p_ax, 4096 * 256, 0);
    split_kernel<<<(3072 * 256) / 256, 256>>>(w_qkv, p_bq, 3072 * 256, 1);

    // 2) QKV projection (tensor cores, fp32 accuracy via 3-term split)
    {
        dim3 grid(3072 / 128, 4096 / 128);
        gemm_mma<<<grid, 256, GEMM_SMEM>>>(p_ax, p_bq, p_qkv, nullptr, 3072);
    }

    // 3) RoPE + split to attention operand layouts
    rope_split_kernel<<<(32 * N_ * 32) / 256, 256>>>(rot);

    // 4) Attention (tensor cores, 3-term split S and PV)
    {
        dim3 grid(N_ / 128, 32);
        attn_mma<<<grid, 256, ATTN_SMEM>>>();
    }

    // 5) split att -> A', w_out -> B' [1024, 3072]
    split_kernel<<<(4096 * 256) / 256, 256>>>(p_att, p_ax, 4096 * 256, 0);
    split_kernel<<<(1024 * 256) / 256, 256>>>(w_out, p_bo, 1024 * 256, 1);

    // 6) Output projection + bias (tensor cores)
    {
        dim3 grid(1024 / 128, 4096 / 128);
        gemm_mma<<<grid, 256, GEMM_SMEM>>>(p_ax, p_bo, out, b_out, 1024);
    }
}